// round 15
// baseline (speedup 1.0000x reference)
#include <cuda_runtime.h>
#include <cuda_bf16.h>
#include <math.h>
#include <stdint.h>

// Problem constants
#define B_Q   256
#define M_MEM 200000
#define D_DIM 384
#define H_DIM 512
#define TOPK  5
#define KC    16
#define TM2   64
#define NSLAB2 3125                     // 200000 / 64 exactly

// ---------------- device scratch ----------------
__device__ float g_act[M_MEM];
__device__ __align__(16) __nv_bfloat16 g_qhi[B_Q * D_DIM];
// packed candidates: [q][slab] records of 12 floats (5 val, 5 idx-bits, 2 pad)
__device__ __align__(16) float g_candT[(size_t)B_Q * NSLAB2 * 12];
__device__ int   g_topk[B_Q * TOPK];
// RNN path scratch
__device__ __align__(16) __nv_bfloat16 g_whh_h[H_DIM * H_DIM];
__device__ __align__(16) __nv_bfloat16 g_whh_l[H_DIM * H_DIM];
__device__ __align__(16) __nv_bfloat16 g_wcat_h[1024 * D_DIM];
__device__ __align__(16) __nv_bfloat16 g_wcat_l[1024 * D_DIM];
__device__ float g_xp[1536 * 1024];
__device__ __align__(16) __nv_bfloat16 g_hbh[2][B_Q * H_DIM];
__device__ __align__(16) __nv_bfloat16 g_hbl[2][B_Q * H_DIM];

// ---------------- helpers ----------------
__device__ __forceinline__ uint32_t smem_u32(const void* p) {
    uint32_t a;
    asm("{ .reg .u64 t; cvta.to.shared.u64 t, %1; cvt.u32.u64 %0, t; }" : "=r"(a) : "l"(p));
    return a;
}
#define CPA16(s, g)  asm volatile("cp.async.cg.shared.global [%0], [%1], 16;" :: "r"(s), "l"(g) : "memory")
#define CPA_COMMIT() asm volatile("cp.async.commit_group;" ::: "memory")
#define CPA_WAIT0()  asm volatile("cp.async.wait_group 0;" ::: "memory")
#define CPA_WAIT1()  asm volatile("cp.async.wait_group 1;" ::: "memory")

__device__ __forceinline__ void ldsm4(uint32_t* r, uint32_t addr) {
    asm volatile("ldmatrix.sync.aligned.m8n8.x4.shared.b16 {%0,%1,%2,%3}, [%4];"
        : "=r"(r[0]), "=r"(r[1]), "=r"(r[2]), "=r"(r[3]) : "r"(addr));
}
__device__ __forceinline__ void mma16816(float* d, const uint32_t* a, uint32_t b0, uint32_t b1) {
    asm volatile("mma.sync.aligned.m16n8k16.row.col.f32.bf16.bf16.f32 "
        "{%0,%1,%2,%3}, {%4,%5,%6,%7}, {%8,%9}, {%0,%1,%2,%3};"
        : "+f"(d[0]), "+f"(d[1]), "+f"(d[2]), "+f"(d[3])
        : "r"(a[0]), "r"(a[1]), "r"(a[2]), "r"(a[3]), "r"(b0), "r"(b1));
}
__device__ __forceinline__ void splt2(float x, float y, uint32_t& hw, uint32_t& lw) {
    __nv_bfloat16 hx = __float2bfloat16(x), hy = __float2bfloat16(y);
    __nv_bfloat16 lx = __float2bfloat16(x - __bfloat162float(hx));
    __nv_bfloat16 ly = __float2bfloat16(y - __bfloat162float(hy));
    __nv_bfloat162 hp = __halves2bfloat162(hx, hy);
    __nv_bfloat162 lp = __halves2bfloat162(lx, ly);
    hw = *(uint32_t*)&hp; lw = *(uint32_t*)&lp;
}
__device__ __forceinline__ uint32_t pk2hi(float x, float y) {
    __nv_bfloat162 hp = __halves2bfloat162(__float2bfloat16(x), __float2bfloat16(y));
    return *(uint32_t*)&hp;
}

__device__ __forceinline__ bool better(float v, int i, float w, int j) {
    return (v > w) || (v == w && i < j);
}
template <int K>
__device__ __forceinline__ void insK(float v, int i, float* tv, int* ti) {
    if (!better(v, i, tv[K - 1], ti[K - 1])) return;
#pragma unroll
    for (int r = 0; r < K; r++) {
        if (better(v, i, tv[r], ti[r])) {
            float fv = tv[r]; int fi = ti[r];
            tv[r] = v; ti[r] = i;
            v = fv; i = fi;
        }
    }
}
#define ins5 insK<TOPK>

// ---------------- kernel A1: center (redundant per block) + activations ----------------
__global__ void k_actc(const float* __restrict__ coords, const float* __restrict__ sw) {
    __shared__ float sx[256], sy[256];
    int tid = threadIdx.x;
    float x = 0.f, y = 0.f;
    for (int i = tid; i < H_DIM; i += 256) { x += sw[2 * i]; y += sw[2 * i + 1]; }
    sx[tid] = x; sy[tid] = y;
    __syncthreads();
    for (int o = 128; o > 0; o >>= 1) {
        if (tid < o) { sx[tid] += sx[tid + o]; sy[tid] += sy[tid + o]; }
        __syncthreads();
    }
    float cx = sx[0] / (float)H_DIM, cy = sy[0] / (float)H_DIM;
    int i = blockIdx.x * blockDim.x + tid;
    if (i < M_MEM) {
        float dx = coords[2 * i] - cx;
        float dy = coords[2 * i + 1] - cy;
        g_act[i] = 1.0f / (1.0f + sqrtf(dx * dx + dy * dy));
    }
}

// ---------------- kernel A2: normalize queries -> bf16 hi ----------------
__global__ void k_qnorm(const float* __restrict__ q) {
    __shared__ float red[128];
    int b = blockIdx.x, tid = threadIdx.x;
    float s = 0.f;
    for (int d = tid; d < D_DIM; d += 128) {
        float v = q[(size_t)b * D_DIM + d];
        s += v * v;
    }
    red[tid] = s;
    __syncthreads();
    for (int o = 64; o > 0; o >>= 1) {
        if (tid < o) red[tid] += red[tid + o];
        __syncthreads();
    }
    float r = 1.0f / fmaxf(sqrtf(red[0]), 1e-8f);
    for (int d = tid; d < D_DIM; d += 128)
        g_qhi[(size_t)b * D_DIM + d] = __float2bfloat16(q[(size_t)b * D_DIM + d] * r);
}

// ---------------- kernel A3: weight split prep ----------------
__global__ void k_prep(const float* __restrict__ Whh, const float* __restrict__ Wih,
                       const float* __restrict__ gW) {
    int i = blockIdx.x * blockDim.x + threadIdx.x;
    if (i < H_DIM * H_DIM) {
        float v = Whh[i];
        __nv_bfloat16 h = __float2bfloat16(v);
        g_whh_h[i] = h;
        g_whh_l[i] = __float2bfloat16(v - __bfloat162float(h));
    } else if (i < H_DIM * H_DIM + 1024 * D_DIM) {
        int j = i - H_DIM * H_DIM;
        int row = j / D_DIM, col = j % D_DIM;
        float v = (row < 512) ? Wih[row * D_DIM + col] : gW[(row - 512) * D_DIM + col];
        __nv_bfloat16 h = __float2bfloat16(v);
        g_wcat_h[j] = h;
        g_wcat_l[j] = __float2bfloat16(v - __bfloat162float(h));
    }
}

// ---------------- kernel B: 1-term coarse sims, TM=64, 2 CTAs/SM ----------------
// single stage: A 64x272 at 1024, B 256x272 at 18432. total smem 88064.
#define SA3   1024
#define SB3   18432
#define SIMS_SMEM 88064
#define E_STG 1024                      // epilogue staging: 256 x 69 f32 = 70656
#define ESTR  69                        // stride 69: bank step 5 (coprime 32) -> conflict-free

__global__ __launch_bounds__(256, 2) void k_sims_mma(const float* __restrict__ mem) {
    extern __shared__ char smem[];
    const uint32_t sb = smem_u32(smem);
    float* s_rn  = (float*)smem;                 // 64 f32
    float* s_act = (float*)(smem + 256);         // 64 f32

    const int tid = threadIdx.x;
    const int l   = tid & 31;
    const int w   = tid >> 5;       // 0..7
    const int wm  = w & 1;          // rows wm*32..+32
    const int wn  = w >> 1;         // queries wn*64..+64
    const int m0  = blockIdx.x * TM2;

    if (tid < 64) s_act[tid] = g_act[m0 + tid];

    float acc[2][8][4];
#pragma unroll
    for (int a = 0; a < 2; a++)
#pragma unroll
        for (int p = 0; p < 8; p++)
#pragma unroll
            for (int r = 0; r < 4; r++) acc[a][p][r] = 0.f;

    // A coalesced: warp w owns rows w*8..w*8+7
    const int ar0 = w * 8;
    const float* abase = mem + (size_t)(m0 + ar0) * D_DIM + l * 4;
    float nsq8[8];
#pragma unroll
    for (int r = 0; r < 8; r++) nsq8[r] = 0.f;

    const uint32_t aB0 = sb + SA3 + (uint32_t)((wm * 32 + (l & 15)) * 272 + (l >> 4) * 16);
    const uint32_t bB0 = sb + SB3 + (uint32_t)((wn * 64 + (l & 15)) * 272 + (l >> 4) * 16);
    const int phase = blockIdx.x & 1;

#pragma unroll 1
    for (int ci = 0; ci < 3; ci++) {
        const int c = (ci + phase) % 3;   // desynchronize partner CTAs

        // B chunk via cp.async (L2-hot)
#pragma unroll
        for (int i = 0; i < 16; i++) {
            int idx = i * 256 + tid;
            int row = idx >> 4, s = idx & 15;
            size_t go = (size_t)row * D_DIM + c * 128 + s * 8;
            CPA16(sb + SB3 + (uint32_t)(row * 272 + s * 16), (const void*)(g_qhi + go));
        }
        CPA_COMMIT();

        // A chunk: coalesced LDG.128 per row, convert, STS
        {
            float4 av[8];
#pragma unroll
            for (int r = 0; r < 8; r++)
                av[r] = *(const float4*)(abase + (size_t)r * D_DIM + c * 128);
#pragma unroll
            for (int r = 0; r < 8; r++) {
                float4 v = av[r];
                nsq8[r] += v.x * v.x + v.y * v.y + v.z * v.z + v.w * v.w;
                uint32_t h0 = pk2hi(v.x, v.y), h1 = pk2hi(v.z, v.w);
                *(uint2*)(smem + SA3 + (ar0 + r) * 272 + l * 8) = make_uint2(h0, h1);
            }
        }
        CPA_WAIT0();
        __syncthreads();

        // GEMM: 8 k16 steps, B fragments double-buffered across kk
        {
            uint32_t bh[2][16];
            uint32_t ah[2][4];
#pragma unroll
            for (int pp = 0; pp < 4; pp++)
                ldsm4(bh[0] + pp * 4, bB0 + (uint32_t)(pp * 16 * 272));
#pragma unroll
            for (int kk = 0; kk < 8; kk++) {
                const int cur = kk & 1, nxt = cur ^ 1;
                if (kk < 7) {
#pragma unroll
                    for (int pp = 0; pp < 4; pp++)
                        ldsm4(bh[nxt] + pp * 4, bB0 + (uint32_t)(pp * 16 * 272 + (kk + 1) * 32));
                }
                // hoist both A ldsm before MMAs
                ldsm4(ah[0], aB0 + (uint32_t)(kk * 32));
                ldsm4(ah[1], aB0 + (uint32_t)(16 * 272 + kk * 32));
#pragma unroll
                for (int a = 0; a < 2; a++)
#pragma unroll
                    for (int p = 0; p < 8; p++) {
                        int pp = p >> 1, hi = p & 1;
                        mma16816(acc[a][p], ah[a], bh[cur][pp * 4 + hi], bh[cur][pp * 4 + hi + 2]);
                    }
            }
        }
        __syncthreads();   // all reads done before next chunk overwrites stage
    }

    // ---- norms: per-row warp reduction ----
#pragma unroll
    for (int r = 0; r < 8; r++) {
        float s = nsq8[r];
#pragma unroll
        for (int o = 16; o > 0; o >>= 1) s += __shfl_xor_sync(0xffffffff, s, o);
        if (l == 0) s_rn[ar0 + r] = 1.0f / fmaxf(sqrtf(s), 1e-8f);
    }
    __syncthreads();

    // ---- epilogue: scale + bias, stage query-major [256][ESTR=69] ----
    float* stg = (float*)(smem + E_STG);
#pragma unroll
    for (int a = 0; a < 2; a++) {
        int mA = wm * 32 + a * 16 + (l >> 2);
        float rnA = s_rn[mA],     acA = s_act[mA];
        float rnB = s_rn[mA + 8], acB = s_act[mA + 8];
#pragma unroll
        for (int p = 0; p < 8; p++) {
            int q = wn * 64 + p * 8 + (l & 3) * 2;
            stg[q * ESTR + mA]           = acc[a][p][0] * rnA + acA;
            stg[(q + 1) * ESTR + mA]     = acc[a][p][1] * rnA + acA;
            stg[q * ESTR + mA + 8]       = acc[a][p][2] * rnB + acB;
            stg[(q + 1) * ESTR + mA + 8] = acc[a][p][3] * rnB + acB;
        }
    }
    __syncthreads();

    // ---- top-5: one thread per query over 64 m (scalar, conflict-free); packed store ----
    {
        const int q = tid;
        float tv[TOPK]; int ti[TOPK];
#pragma unroll
        for (int r = 0; r < TOPK; r++) { tv[r] = -3.4e38f; ti[r] = 0x7fffffff; }
        const float* col = stg + q * ESTR;
#pragma unroll 8
        for (int i = 0; i < 64; i++)
            ins5(col[i], m0 + i, tv, ti);
        float4* rec = (float4*)(g_candT + ((size_t)q * NSLAB2 + blockIdx.x) * 12);
        rec[0] = make_float4(tv[0], tv[1], tv[2], tv[3]);
        rec[1] = make_float4(tv[4], __int_as_float(ti[0]), __int_as_float(ti[1]),
                             __int_as_float(ti[2]));
        rec[2] = make_float4(__int_as_float(ti[3]), __int_as_float(ti[4]), 0.f, 0.f);
    }
}

// ---------------- kernel C: fused merge -> top-16 -> exact refine -> top-5 ----------------
template <int K>
__device__ __forceinline__ void mergeK(float* av, int* ai, const float* bv, const int* bi) {
    float ov[K]; int oi[K];
    int ia = 0, ib = 0;
#pragma unroll
    for (int r = 0; r < K; r++) {
        bool ta = (ib >= K) || (ia < K && better(av[ia], ai[ia], bv[ib], bi[ib]));
        if (ta) { ov[r] = av[ia]; oi[r] = ai[ia]; ia++; }
        else    { ov[r] = bv[ib]; oi[r] = bi[ib]; ib++; }
    }
#pragma unroll
    for (int r = 0; r < K; r++) { av[r] = ov[r]; ai[r] = oi[r]; }
}

__global__ __launch_bounds__(256) void k_mergeref(const float* __restrict__ query,
                                                 const float* __restrict__ mem) {
    __shared__ float sv[256][KC];
    __shared__ int   si[256][KC];
    __shared__ float qv[D_DIM];
    __shared__ float s_qn[8];
    __shared__ float s_sims[KC];

    const int q = blockIdx.x, tid = threadIdx.x;
    const int lane = tid & 31, wr = tid >> 5;

    float p = 0.f;
    for (int d = tid; d < D_DIM; d += 256) {
        float v = query[(size_t)q * D_DIM + d];
        qv[d] = v;
        p += v * v;
    }
#pragma unroll
    for (int o = 16; o > 0; o >>= 1) p += __shfl_xor_sync(0xffffffff, p, o);
    if (lane == 0) s_qn[wr] = p;

    // phase 1: coalesced scan of packed candidate records
    float tv[KC]; int ti[KC];
#pragma unroll
    for (int r = 0; r < KC; r++) { tv[r] = -3.4e38f; ti[r] = 0x7fffffff; }
    const float* qbase = g_candT + (size_t)q * NSLAB2 * 12;
    for (int s = tid; s < NSLAB2; s += 256) {
        const float4* rec = (const float4*)(qbase + (size_t)s * 12);
        float4 r0 = rec[0], r1 = rec[1], r2 = rec[2];
        insK<KC>(r0.x, __float_as_int(r1.y), tv, ti);
        insK<KC>(r0.y, __float_as_int(r1.z), tv, ti);
        insK<KC>(r0.z, __float_as_int(r1.w), tv, ti);
        insK<KC>(r0.w, __float_as_int(r2.x), tv, ti);
        insK<KC>(r1.x, __float_as_int(r2.y), tv, ti);
    }
#pragma unroll
    for (int r = 0; r < KC; r++) { sv[tid][r] = tv[r]; si[tid][r] = ti[r]; }
    __syncthreads();
    for (int o = 128; o > 0; o >>= 1) {
        if (tid < o) mergeK<KC>(sv[tid], si[tid], sv[tid + o], si[tid + o]);
        __syncthreads();
    }

    float qs = 0.f;
#pragma unroll
    for (int i = 0; i < 8; i++) qs += s_qn[i];
    float rq = 1.0f / fmaxf(sqrtf(qs), 1e-8f);

    for (int c = wr; c < KC; c += 8) {
        int mi = si[0][c];
        const float* mv = mem + (size_t)mi * D_DIM;
        float dot = 0.f, msq = 0.f;
        for (int d = lane; d < D_DIM; d += 32) {
            float m = mv[d];
            dot += qv[d] * m;
            msq += m * m;
        }
#pragma unroll
        for (int o = 16; o > 0; o >>= 1) {
            dot += __shfl_xor_sync(0xffffffff, dot, o);
            msq += __shfl_xor_sync(0xffffffff, msq, o);
        }
        if (lane == 0)
            s_sims[c] = dot * rq / fmaxf(sqrtf(msq), 1e-8f) + g_act[mi];
    }
    __syncthreads();

    if (tid == 0) {
        float fv[TOPK]; int fi[TOPK];
#pragma unroll
        for (int r = 0; r < TOPK; r++) { fv[r] = -3.4e38f; fi[r] = 0x7fffffff; }
        for (int c = 0; c < KC; c++)
            ins5(s_sims[c], si[0][c], fv, fi);
#pragma unroll
        for (int r = 0; r < TOPK; r++)
            g_topk[q * TOPK + r] = fi[r];
    }
}

// ---------------- kernel D1: x_proj + gate GEMM [1536 x 1024 x 384], fused h0 ----------------
#define XP_AHI 0
#define XP_ALO 34816
#define XP_BHI 69632
#define XP_BLO 104448
#define XP_SMEM 139264

__global__ __launch_bounds__(256, 1) void k_xproj(
    const float* __restrict__ query, const float* __restrict__ mem,
    const float* __restrict__ bih, const float* __restrict__ gb,
    const float* __restrict__ bhh)
{
    extern __shared__ char smem[];
    const uint32_t sb = smem_u32(smem);
    const int tid = threadIdx.x, l = tid & 31, w = tid >> 5;
    const int wm = w & 3, wn = w >> 2;
    const int bm = blockIdx.x, bn = blockIdx.y;

    const int lrow = tid >> 1, kh = tid & 1;
    int r = bm * 128 + lrow;
    int t = r >> 8, q = r & 255;
    const float* aptr;
    if (t == 0) aptr = query + (size_t)q * D_DIM;
    else        aptr = mem + (size_t)g_topk[q * TOPK + t - 1] * D_DIM;
    aptr += kh * 64;

    float acc[2][8][4];
#pragma unroll
    for (int a = 0; a < 2; a++)
#pragma unroll
        for (int p = 0; p < 8; p++)
#pragma unroll
            for (int rr = 0; rr < 4; rr++) acc[a][p][rr] = 0.f;

#pragma unroll 1
    for (int c = 0; c < 3; c++) {
        __syncthreads();
#pragma unroll
        for (int i = 0; i < 8; i++) {
            int idx = i * 256 + tid;
            int row = idx >> 4, s = idx & 15;
            uint32_t d = sb + (uint32_t)(row * 272 + s * 16);
            size_t go = (size_t)(bn * 128 + row) * D_DIM + c * 128 + s * 8;
            CPA16(d + XP_BHI, (const void*)(g_wcat_h + go));
            CPA16(d + XP_BLO, (const void*)(g_wcat_l + go));
        }
        CPA_COMMIT();
        {
            char* ah = smem + XP_AHI;
            char* al = smem + XP_ALO;
            const float4* src = (const float4*)(aptr + c * 128);
#pragma unroll
            for (int i = 0; i < 16; i++) {
                float4 v = src[i];
                uint32_t h0, l0, h1, l1;
                splt2(v.x, v.y, h0, l0);
                splt2(v.z, v.w, h1, l1);
                uint32_t so = (uint32_t)(lrow * 272 + kh * 128 + i * 8);
                *(uint2*)(ah + so) = make_uint2(h0, h1);
                *(uint2*)(al + so) = make_uint2(l0, l1);
            }
        }
        CPA_WAIT0();
        __syncthreads();

        const uint32_t aB = sb + XP_AHI + (uint32_t)((wm * 32 + (l & 15)) * 272 + (l >> 4) * 16);
        const uint32_t bB = sb + XP_BHI + (uint32_t)((wn * 64 + (l & 15)) * 272 + (l >> 4) * 16);
#pragma unroll 1
        for (int kk = 0; kk < 8; kk++) {
            uint32_t bh[16], bl[16];
#pragma unroll
            for (int pp = 0; pp < 4; pp++) {
                uint32_t ba = bB + (uint32_t)(pp * 16 * 272 + kk * 32);
                ldsm4(bh + pp * 4, ba);
                ldsm4(bl + pp * 4, ba + (XP_BLO - XP_BHI));
            }
#pragma unroll
            for (int a = 0; a < 2; a++) {
                uint32_t ah4[4], al4[4];
                uint32_t aa = aB + (uint32_t)(a * 16 * 272 + kk * 32);
                ldsm4(ah4, aa);
                ldsm4(al4, aa + (XP_ALO - XP_AHI));
#pragma unroll
                for (int p = 0; p < 8; p++) {
                    int pp = p >> 1, hi = p & 1;
                    mma16816(acc[a][p], ah4, bh[pp * 4 + hi], bh[pp * 4 + hi + 2]);
                    mma16816(acc[a][p], ah4, bl[pp * 4 + hi], bl[pp * 4 + hi + 2]);
                    mma16816(acc[a][p], al4, bh[pp * 4 + hi], bh[pp * 4 + hi + 2]);
                }
            }
        }
    }

    const bool fuse_h0 = (bm < 2) && (bn < 4);
#pragma unroll
    for (int a = 0; a < 2; a++) {
        int rA = bm * 128 + wm * 32 + a * 16 + (l >> 2);
#pragma unroll
        for (int p = 0; p < 8; p++) {
            int cg = bn * 128 + wn * 64 + p * 8 + (l & 3) * 2;
            float b0 = (cg < 512) ? bih[cg] : gb[cg - 512];
            float b1 = (cg < 512) ? bih[cg + 1] : gb[cg + 1 - 512];
            float v00 = acc[a][p][0] + b0, v01 = acc[a][p][1] + b1;
            float v10 = acc[a][p][2] + b0, v11 = acc[a][p][3] + b1;
            g_xp[(size_t)rA * 1024 + cg]           = v00;
            g_xp[(size_t)rA * 1024 + cg + 1]       = v01;
            g_xp[(size_t)(rA + 8) * 1024 + cg]     = v10;
            g_xp[(size_t)(rA + 8) * 1024 + cg + 1] = v11;
            if (fuse_h0) {
                float bh0 = bhh[cg], bh1 = bhh[cg + 1];
                float h00 = tanhf(v00 + bh0), h01 = tanhf(v01 + bh1);
                float h10 = tanhf(v10 + bh0), h11 = tanhf(v11 + bh1);
                size_t o0 = (size_t)rA * H_DIM + cg;
                size_t o1 = (size_t)(rA + 8) * H_DIM + cg;
                __nv_bfloat16 q00 = __float2bfloat16(h00), q01 = __float2bfloat16(h01);
                __nv_bfloat16 q10 = __float2bfloat16(h10), q11 = __float2bfloat16(h11);
                g_hbh[0][o0] = q00; g_hbh[0][o0 + 1] = q01;
                g_hbh[0][o1] = q10; g_hbh[0][o1 + 1] = q11;
                g_hbl[0][o0] = __float2bfloat16(h00 - __bfloat162float(q00));
                g_hbl[0][o0 + 1] = __float2bfloat16(h01 - __bfloat162float(q01));
                g_hbl[0][o1] = __float2bfloat16(h10 - __bfloat162float(q10));
                g_hbl[0][o1 + 1] = __float2bfloat16(h11 - __bfloat162float(q11));
            }
        }
    }
}

// ---------------- kernel D3: recurrence step GEMM, 32 CTAs, double-buffered ----------------
// t==5: gate mix fused, writes final output.
#define ST2_AHI 0
#define ST2_ALO 17408
#define ST2_BHI 34816
#define ST2_BLO 52224
#define ST2_STG 69632
#define ST2_SMEM (2 * ST2_STG)   // 139264

__global__ __launch_bounds__(256, 1) void k_step(int t, const float* __restrict__ bhh,
                                                 float* __restrict__ out) {
    extern __shared__ char smem[];
    const uint32_t sb = smem_u32(smem);
    const int tid = threadIdx.x, l = tid & 31, w = tid >> 5;
    const int wm = w & 3, wn = w >> 2;   // warp tile 16 x 32
    const int mt = blockIdx.x, nt = blockIdx.y;   // (4, 8)
    const int bin = (t + 1) & 1, bout = t & 1;
    const __nv_bfloat16* Ah = g_hbh[bin];
    const __nv_bfloat16* Al = g_hbl[bin];

    float acc[4][4];
#pragma unroll
    for (int p = 0; p < 4; p++)
#pragma unroll
        for (int rr = 0; rr < 4; rr++) acc[p][rr] = 0.f;

#define ST_LOAD(cc) do {                                                      \
    uint32_t stn = sb + ((cc) & 1) * ST2_STG;                                 \
    _Pragma("unroll")                                                         \
    for (int i = 0; i < 4; i++) {                                             \
        int idx = i * 256 + tid;                                              \
        int row = idx >> 4, s = idx & 15;                                     \
        uint32_t d = stn + (uint32_t)(row * 272 + s * 16);                    \
        size_t goA = (size_t)(mt * 64 + row) * H_DIM + (cc) * 128 + s * 8;    \
        size_t goB = (size_t)(nt * 64 + row) * H_DIM + (cc) * 128 + s * 8;    \
        CPA16(d + ST2_AHI, (const void*)(Ah + goA));                          \
        CPA16(d + ST2_ALO, (const void*)(Al + goA));                          \
        CPA16(d + ST2_BHI, (const void*)(g_whh_h + goB));                     \
        CPA16(d + ST2_BLO, (const void*)(g_whh_l + goB));                     \
    }                                                                         \
    CPA_COMMIT();                                                             \
} while (0)

    ST_LOAD(0);

#pragma unroll 1
    for (int c = 0; c < 4; c++) {
        __syncthreads();
        if (c < 3) ST_LOAD(c + 1);
        if (c < 3) CPA_WAIT1(); else CPA_WAIT0();
        __syncthreads();

        const uint32_t st = sb + (c & 1) * ST2_STG;
        const uint32_t aB = st + ST2_AHI + (uint32_t)((wm * 16 + (l & 15)) * 272 + (l >> 4) * 16);
        const uint32_t bB = st + ST2_BHI + (uint32_t)((wn * 32 + (l & 15)) * 272 + (l >> 4) * 16);
#pragma unroll 1
        for (int kk = 0; kk < 8; kk++) {
            uint32_t bh[8], bl[8];
#pragma unroll
            for (int pp = 0; pp < 2; pp++) {
                uint32_t ba = bB + (uint32_t)(pp * 16 * 272 + kk * 32);
                ldsm4(bh + pp * 4, ba);
                ldsm4(bl + pp * 4, ba + (ST2_BLO - ST2_BHI));
            }
            uint32_t ah4[4], al4[4];
            ldsm4(ah4, aB + (uint32_t)(kk * 32));
            ldsm4(al4, aB + (uint32_t)(kk * 32) + (ST2_ALO - ST2_AHI));
#pragma unroll
            for (int p = 0; p < 4; p++) {
                int pp = p >> 1, hi = p & 1;
                mma16816(acc[p], ah4, bh[pp * 4 + hi], bh[pp * 4 + hi + 2]);
                mma16816(acc[p], ah4, bl[pp * 4 + hi], bl[pp * 4 + hi + 2]);
                mma16816(acc[p], al4, bh[pp * 4 + hi], bh[pp * 4 + hi + 2]);
            }
        }
    }

    int q0 = mt * 64 + wm * 16 + (l >> 2);
#pragma unroll
    for (int p = 0; p < 4; p++) {
        int h = nt * 64 + wn * 32 + p * 8 + (l & 3) * 2;
#pragma unroll
        for (int rr = 0; rr < 4; rr++) {
            int qq = q0 + ((rr >> 1) ? 8 : 0);
            int hh = h + (rr & 1);
            float v = acc[p][rr] + g_xp[(size_t)(t * 256 + qq) * 1024 + hh] + bhh[hh];
            float ht = tanhf(v);
            if (t == TOPK) {
                float gpre = g_xp[(size_t)qq * 1024 + 512 + hh];
                float g = 1.0f / (1.0f + expf(-gpre));
                float proj = g_xp[(size_t)qq * 1024 + hh];
                out[(size_t)qq * H_DIM + hh] = g * ht + (1.0f - g) * proj;
            } else {
                size_t o = (size_t)qq * H_DIM + hh;
                __nv_bfloat16 hb = __float2bfloat16(ht);
                g_hbh[bout][o] = hb;
                g_hbl[bout][o] = __float2bfloat16(ht - __bfloat162float(hb));
            }
        }
    }
#undef ST_LOAD
}

// ---------------- launch ----------------
extern "C" void kernel_launch(void* const* d_in, const int* in_sizes, int n_in,
                              void* d_out, int out_size) {
    const float* query  = (const float*)d_in[0];
    const float* mem    = (const float*)d_in[1];
    const float* coords = (const float*)d_in[2];
    const float* sw     = (const float*)d_in[3];
    const float* Wih    = (const float*)d_in[4];
    const float* bih    = (const float*)d_in[5];
    const float* Whh    = (const float*)d_in[6];
    const float* bhh    = (const float*)d_in[7];
    const float* gW     = (const float*)d_in[8];
    const float* gb     = (const float*)d_in[9];
    float* out = (float*)d_out;

    cudaFuncSetAttribute(k_sims_mma, cudaFuncAttributeMaxDynamicSharedMemorySize, SIMS_SMEM);
    cudaFuncSetAttribute(k_xproj,    cudaFuncAttributeMaxDynamicSharedMemorySize, XP_SMEM);
    cudaFuncSetAttribute(k_step,     cudaFuncAttributeMaxDynamicSharedMemorySize, ST2_SMEM);

    // k_sims as launch #4 -> lands in the ncu capture window
    k_actc<<<(M_MEM + 255) / 256, 256>>>(coords, sw);
    k_qnorm<<<B_Q, 128>>>(query);
    k_prep<<<(H_DIM * H_DIM + 1024 * D_DIM + 255) / 256, 256>>>(Whh, Wih, gW);
    k_sims_mma<<<NSLAB2, 256, SIMS_SMEM>>>(mem);
    k_mergeref<<<B_Q, 256>>>(query, mem);
    k_xproj<<<dim3(12, 8), 256, XP_SMEM>>>(query, mem, bih, gb, bhh);
    for (int t = 1; t <= TOPK; t++)
        k_step<<<dim3(4, 8), 256, ST2_SMEM>>>(t, bhh, out);
}

// round 16
// speedup vs baseline: 1.1477x; 1.1477x over previous
#include <cuda_runtime.h>
#include <cuda_bf16.h>
#include <math.h>
#include <stdint.h>

// Problem constants
#define B_Q   256
#define M_MEM 200000
#define D_DIM 384
#define H_DIM 512
#define TOPK  5
#define KC    16
#define NC    3                         // candidates kept per slab
#define TM2   64
#define NSLAB2 3125                     // 200000 / 64 exactly

// ---------------- device scratch ----------------
__device__ float g_act[M_MEM];
__device__ __align__(16) __nv_bfloat16 g_qhi[B_Q * D_DIM];
// packed candidates: [q][slab] records of 8 floats (3 val, 3 idx-bits, 2 pad)
__device__ __align__(16) float g_candT[(size_t)B_Q * NSLAB2 * 8];
__device__ int   g_topk[B_Q * TOPK];
// RNN path scratch
__device__ __align__(16) __nv_bfloat16 g_whh_h[H_DIM * H_DIM];
__device__ __align__(16) __nv_bfloat16 g_whh_l[H_DIM * H_DIM];
__device__ __align__(16) __nv_bfloat16 g_wcat_h[1024 * D_DIM];
__device__ __align__(16) __nv_bfloat16 g_wcat_l[1024 * D_DIM];
__device__ float g_xp[1536 * 1024];
__device__ __align__(16) __nv_bfloat16 g_hbh[2][B_Q * H_DIM];
__device__ __align__(16) __nv_bfloat16 g_hbl[2][B_Q * H_DIM];

// ---------------- helpers ----------------
__device__ __forceinline__ uint32_t smem_u32(const void* p) {
    uint32_t a;
    asm("{ .reg .u64 t; cvta.to.shared.u64 t, %1; cvt.u32.u64 %0, t; }" : "=r"(a) : "l"(p));
    return a;
}
#define CPA16(s, g)  asm volatile("cp.async.cg.shared.global [%0], [%1], 16;" :: "r"(s), "l"(g) : "memory")
#define CPA_COMMIT() asm volatile("cp.async.commit_group;" ::: "memory")
#define CPA_WAIT0()  asm volatile("cp.async.wait_group 0;" ::: "memory")
#define CPA_WAIT1()  asm volatile("cp.async.wait_group 1;" ::: "memory")

__device__ __forceinline__ void ldsm4(uint32_t* r, uint32_t addr) {
    asm volatile("ldmatrix.sync.aligned.m8n8.x4.shared.b16 {%0,%1,%2,%3}, [%4];"
        : "=r"(r[0]), "=r"(r[1]), "=r"(r[2]), "=r"(r[3]) : "r"(addr));
}
__device__ __forceinline__ void mma16816(float* d, const uint32_t* a, uint32_t b0, uint32_t b1) {
    asm volatile("mma.sync.aligned.m16n8k16.row.col.f32.bf16.bf16.f32 "
        "{%0,%1,%2,%3}, {%4,%5,%6,%7}, {%8,%9}, {%0,%1,%2,%3};"
        : "+f"(d[0]), "+f"(d[1]), "+f"(d[2]), "+f"(d[3])
        : "r"(a[0]), "r"(a[1]), "r"(a[2]), "r"(a[3]), "r"(b0), "r"(b1));
}
__device__ __forceinline__ void splt2(float x, float y, uint32_t& hw, uint32_t& lw) {
    __nv_bfloat16 hx = __float2bfloat16(x), hy = __float2bfloat16(y);
    __nv_bfloat16 lx = __float2bfloat16(x - __bfloat162float(hx));
    __nv_bfloat16 ly = __float2bfloat16(y - __bfloat162float(hy));
    __nv_bfloat162 hp = __halves2bfloat162(hx, hy);
    __nv_bfloat162 lp = __halves2bfloat162(lx, ly);
    hw = *(uint32_t*)&hp; lw = *(uint32_t*)&lp;
}
__device__ __forceinline__ uint32_t pk2hi(float x, float y) {
    __nv_bfloat162 hp = __halves2bfloat162(__float2bfloat16(x), __float2bfloat16(y));
    return *(uint32_t*)&hp;
}

__device__ __forceinline__ bool better(float v, int i, float w, int j) {
    return (v > w) || (v == w && i < j);
}
template <int K>
__device__ __forceinline__ void insK(float v, int i, float* tv, int* ti) {
    if (!better(v, i, tv[K - 1], ti[K - 1])) return;
#pragma unroll
    for (int r = 0; r < K; r++) {
        if (better(v, i, tv[r], ti[r])) {
            float fv = tv[r]; int fi = ti[r];
            tv[r] = v; ti[r] = i;
            v = fv; i = fi;
        }
    }
}
#define ins5 insK<TOPK>

// ---------------- kernel A1: center (redundant per block) + activations ----------------
__global__ void k_actc(const float* __restrict__ coords, const float* __restrict__ sw) {
    __shared__ float sx[256], sy[256];
    int tid = threadIdx.x;
    float x = 0.f, y = 0.f;
    for (int i = tid; i < H_DIM; i += 256) { x += sw[2 * i]; y += sw[2 * i + 1]; }
    sx[tid] = x; sy[tid] = y;
    __syncthreads();
    for (int o = 128; o > 0; o >>= 1) {
        if (tid < o) { sx[tid] += sx[tid + o]; sy[tid] += sy[tid + o]; }
        __syncthreads();
    }
    float cx = sx[0] / (float)H_DIM, cy = sy[0] / (float)H_DIM;
    int i = blockIdx.x * blockDim.x + tid;
    if (i < M_MEM) {
        float dx = coords[2 * i] - cx;
        float dy = coords[2 * i + 1] - cy;
        g_act[i] = 1.0f / (1.0f + sqrtf(dx * dx + dy * dy));
    }
}

// ---------------- kernel A2: normalize queries -> bf16 hi ----------------
__global__ void k_qnorm(const float* __restrict__ q) {
    __shared__ float red[128];
    int b = blockIdx.x, tid = threadIdx.x;
    float s = 0.f;
    for (int d = tid; d < D_DIM; d += 128) {
        float v = q[(size_t)b * D_DIM + d];
        s += v * v;
    }
    red[tid] = s;
    __syncthreads();
    for (int o = 64; o > 0; o >>= 1) {
        if (tid < o) red[tid] += red[tid + o];
        __syncthreads();
    }
    float r = 1.0f / fmaxf(sqrtf(red[0]), 1e-8f);
    for (int d = tid; d < D_DIM; d += 128)
        g_qhi[(size_t)b * D_DIM + d] = __float2bfloat16(q[(size_t)b * D_DIM + d] * r);
}

// ---------------- kernel A3: weight split prep ----------------
__global__ void k_prep(const float* __restrict__ Whh, const float* __restrict__ Wih,
                       const float* __restrict__ gW) {
    int i = blockIdx.x * blockDim.x + threadIdx.x;
    if (i < H_DIM * H_DIM) {
        float v = Whh[i];
        __nv_bfloat16 h = __float2bfloat16(v);
        g_whh_h[i] = h;
        g_whh_l[i] = __float2bfloat16(v - __bfloat162float(h));
    } else if (i < H_DIM * H_DIM + 1024 * D_DIM) {
        int j = i - H_DIM * H_DIM;
        int row = j / D_DIM, col = j % D_DIM;
        float v = (row < 512) ? Wih[row * D_DIM + col] : gW[(row - 512) * D_DIM + col];
        __nv_bfloat16 h = __float2bfloat16(v);
        g_wcat_h[j] = h;
        g_wcat_l[j] = __float2bfloat16(v - __bfloat162float(h));
    }
}

// ---------------- kernel B: 1-term coarse sims, TM=64, 2 CTAs/SM (R14 mainloop) ----------------
// single stage: A 64x272 at 1024, B 256x272 at 18432. total smem 88064.
#define SA3   1024
#define SB3   18432
#define SIMS_SMEM 88064
#define E_STG 1024                      // epilogue staging: 256 x 68 f32 = 69632

__global__ __launch_bounds__(256, 2) void k_sims_mma(const float* __restrict__ mem) {
    extern __shared__ char smem[];
    const uint32_t sb = smem_u32(smem);
    float* s_rn  = (float*)smem;                 // 64 f32
    float* s_act = (float*)(smem + 256);         // 64 f32

    const int tid = threadIdx.x;
    const int l   = tid & 31;
    const int w   = tid >> 5;       // 0..7
    const int wm  = w & 1;          // rows wm*32..+32
    const int wn  = w >> 1;         // queries wn*64..+64
    const int m0  = blockIdx.x * TM2;

    if (tid < 64) s_act[tid] = g_act[m0 + tid];

    float acc[2][8][4];
#pragma unroll
    for (int a = 0; a < 2; a++)
#pragma unroll
        for (int p = 0; p < 8; p++)
#pragma unroll
            for (int r = 0; r < 4; r++) acc[a][p][r] = 0.f;

    // A coalesced: warp w owns rows w*8..w*8+7
    const int ar0 = w * 8;
    const float* abase = mem + (size_t)(m0 + ar0) * D_DIM + l * 4;
    float nsq8[8];
#pragma unroll
    for (int r = 0; r < 8; r++) nsq8[r] = 0.f;

    const uint32_t aB0 = sb + SA3 + (uint32_t)((wm * 32 + (l & 15)) * 272 + (l >> 4) * 16);
    const uint32_t bB0 = sb + SB3 + (uint32_t)((wn * 64 + (l & 15)) * 272 + (l >> 4) * 16);
    const int phase = blockIdx.x & 1;

#pragma unroll 1
    for (int ci = 0; ci < 3; ci++) {
        const int c = (ci + phase) % 3;   // desynchronize partner CTAs

        // B chunk via cp.async (L2-hot)
#pragma unroll
        for (int i = 0; i < 16; i++) {
            int idx = i * 256 + tid;
            int row = idx >> 4, s = idx & 15;
            size_t go = (size_t)row * D_DIM + c * 128 + s * 8;
            CPA16(sb + SB3 + (uint32_t)(row * 272 + s * 16), (const void*)(g_qhi + go));
        }
        CPA_COMMIT();

        // A chunk: coalesced LDG.128 per row, convert, STS
        {
            float4 av[8];
#pragma unroll
            for (int r = 0; r < 8; r++)
                av[r] = *(const float4*)(abase + (size_t)r * D_DIM + c * 128);
#pragma unroll
            for (int r = 0; r < 8; r++) {
                float4 v = av[r];
                nsq8[r] += v.x * v.x + v.y * v.y + v.z * v.z + v.w * v.w;
                uint32_t h0 = pk2hi(v.x, v.y), h1 = pk2hi(v.z, v.w);
                *(uint2*)(smem + SA3 + (ar0 + r) * 272 + l * 8) = make_uint2(h0, h1);
            }
        }
        CPA_WAIT0();
        __syncthreads();

        // GEMM: 8 k16 steps
#pragma unroll
        for (int kk = 0; kk < 8; kk++) {
            uint32_t bh[16];
#pragma unroll
            for (int pp = 0; pp < 4; pp++)
                ldsm4(bh + pp * 4, bB0 + (uint32_t)(pp * 16 * 272 + kk * 32));
#pragma unroll
            for (int a = 0; a < 2; a++) {
                uint32_t ah4[4];
                ldsm4(ah4, aB0 + (uint32_t)(a * 16 * 272 + kk * 32));
#pragma unroll
                for (int p = 0; p < 8; p++) {
                    int pp = p >> 1, hi = p & 1;
                    mma16816(acc[a][p], ah4, bh[pp * 4 + hi], bh[pp * 4 + hi + 2]);
                }
            }
        }
        __syncthreads();   // all reads done before next chunk overwrites stage
    }

    // ---- norms: per-row warp reduction ----
#pragma unroll
    for (int r = 0; r < 8; r++) {
        float s = nsq8[r];
#pragma unroll
        for (int o = 16; o > 0; o >>= 1) s += __shfl_xor_sync(0xffffffff, s, o);
        if (l == 0) s_rn[ar0 + r] = 1.0f / fmaxf(sqrtf(s), 1e-8f);
    }
    __syncthreads();

    // ---- epilogue: scale + bias, stage query-major [256][68] ----
    float* stg = (float*)(smem + E_STG);
#pragma unroll
    for (int a = 0; a < 2; a++) {
        int mA = wm * 32 + a * 16 + (l >> 2);
        float rnA = s_rn[mA],     acA = s_act[mA];
        float rnB = s_rn[mA + 8], acB = s_act[mA + 8];
#pragma unroll
        for (int p = 0; p < 8; p++) {
            int q = wn * 64 + p * 8 + (l & 3) * 2;
            stg[q * 68 + mA]           = acc[a][p][0] * rnA + acA;
            stg[(q + 1) * 68 + mA]     = acc[a][p][1] * rnA + acA;
            stg[q * 68 + mA + 8]       = acc[a][p][2] * rnB + acB;
            stg[(q + 1) * 68 + mA + 8] = acc[a][p][3] * rnB + acB;
        }
    }
    __syncthreads();

    // ---- top-3: one thread per query over 64 m; packed 32B transposed store ----
    {
        const int q = tid;
        float tv[NC]; int ti[NC];
#pragma unroll
        for (int r = 0; r < NC; r++) { tv[r] = -3.4e38f; ti[r] = 0x7fffffff; }
        const float4* col = (const float4*)(stg + q * 68);
#pragma unroll 4
        for (int i = 0; i < 16; i++) {
            float4 v = col[i];
            int mb = m0 + i * 4;
            insK<NC>(v.x, mb,     tv, ti);
            insK<NC>(v.y, mb + 1, tv, ti);
            insK<NC>(v.z, mb + 2, tv, ti);
            insK<NC>(v.w, mb + 3, tv, ti);
        }
        float4* rec = (float4*)(g_candT + ((size_t)q * NSLAB2 + blockIdx.x) * 8);
        rec[0] = make_float4(tv[0], tv[1], tv[2], __int_as_float(ti[0]));
        rec[1] = make_float4(__int_as_float(ti[1]), __int_as_float(ti[2]), 0.f, 0.f);
    }
}

// ---------------- kernel C: fused merge -> top-16 -> exact refine -> top-5 ----------------
template <int K>
__device__ __forceinline__ void mergeK(float* av, int* ai, const float* bv, const int* bi) {
    float ov[K]; int oi[K];
    int ia = 0, ib = 0;
#pragma unroll
    for (int r = 0; r < K; r++) {
        bool ta = (ib >= K) || (ia < K && better(av[ia], ai[ia], bv[ib], bi[ib]));
        if (ta) { ov[r] = av[ia]; oi[r] = ai[ia]; ia++; }
        else    { ov[r] = bv[ib]; oi[r] = bi[ib]; ib++; }
    }
#pragma unroll
    for (int r = 0; r < K; r++) { av[r] = ov[r]; ai[r] = oi[r]; }
}

__global__ __launch_bounds__(256) void k_mergeref(const float* __restrict__ query,
                                                 const float* __restrict__ mem) {
    __shared__ float sv[256][KC];
    __shared__ int   si[256][KC];
    __shared__ float qv[D_DIM];
    __shared__ float s_qn[8];
    __shared__ float s_sims[KC];

    const int q = blockIdx.x, tid = threadIdx.x;
    const int lane = tid & 31, wr = tid >> 5;

    float p = 0.f;
    for (int d = tid; d < D_DIM; d += 256) {
        float v = query[(size_t)q * D_DIM + d];
        qv[d] = v;
        p += v * v;
    }
#pragma unroll
    for (int o = 16; o > 0; o >>= 1) p += __shfl_xor_sync(0xffffffff, p, o);
    if (lane == 0) s_qn[wr] = p;

    // phase 1: coalesced scan of packed 32B candidate records
    float tv[KC]; int ti[KC];
#pragma unroll
    for (int r = 0; r < KC; r++) { tv[r] = -3.4e38f; ti[r] = 0x7fffffff; }
    const float* qbase = g_candT + (size_t)q * NSLAB2 * 8;
    for (int s = tid; s < NSLAB2; s += 256) {
        const float4* rec = (const float4*)(qbase + (size_t)s * 8);
        float4 r0 = rec[0], r1 = rec[1];
        insK<KC>(r0.x, __float_as_int(r0.w), tv, ti);
        insK<KC>(r0.y, __float_as_int(r1.x), tv, ti);
        insK<KC>(r0.z, __float_as_int(r1.y), tv, ti);
    }
#pragma unroll
    for (int r = 0; r < KC; r++) { sv[tid][r] = tv[r]; si[tid][r] = ti[r]; }
    __syncthreads();
    for (int o = 128; o > 0; o >>= 1) {
        if (tid < o) mergeK<KC>(sv[tid], si[tid], sv[tid + o], si[tid + o]);
        __syncthreads();
    }

    float qs = 0.f;
#pragma unroll
    for (int i = 0; i < 8; i++) qs += s_qn[i];
    float rq = 1.0f / fmaxf(sqrtf(qs), 1e-8f);

    for (int c = wr; c < KC; c += 8) {
        int mi = si[0][c];
        const float* mv = mem + (size_t)mi * D_DIM;
        float dot = 0.f, msq = 0.f;
        for (int d = lane; d < D_DIM; d += 32) {
            float m = mv[d];
            dot += qv[d] * m;
            msq += m * m;
        }
#pragma unroll
        for (int o = 16; o > 0; o >>= 1) {
            dot += __shfl_xor_sync(0xffffffff, dot, o);
            msq += __shfl_xor_sync(0xffffffff, msq, o);
        }
        if (lane == 0)
            s_sims[c] = dot * rq / fmaxf(sqrtf(msq), 1e-8f) + g_act[mi];
    }
    __syncthreads();

    if (tid == 0) {
        float fv[TOPK]; int fi[TOPK];
#pragma unroll
        for (int r = 0; r < TOPK; r++) { fv[r] = -3.4e38f; fi[r] = 0x7fffffff; }
        for (int c = 0; c < KC; c++)
            ins5(s_sims[c], si[0][c], fv, fi);
#pragma unroll
        for (int r = 0; r < TOPK; r++)
            g_topk[q * TOPK + r] = fi[r];
    }
}

// ---------------- kernel D1: x_proj + gate GEMM [1536 x 1024 x 384], fused h0 ----------------
#define XP_AHI 0
#define XP_ALO 34816
#define XP_BHI 69632
#define XP_BLO 104448
#define XP_SMEM 139264

__global__ __launch_bounds__(256, 1) void k_xproj(
    const float* __restrict__ query, const float* __restrict__ mem,
    const float* __restrict__ bih, const float* __restrict__ gb,
    const float* __restrict__ bhh)
{
    extern __shared__ char smem[];
    const uint32_t sb = smem_u32(smem);
    const int tid = threadIdx.x, l = tid & 31, w = tid >> 5;
    const int wm = w & 3, wn = w >> 2;
    const int bm = blockIdx.x, bn = blockIdx.y;

    const int lrow = tid >> 1, kh = tid & 1;
    int r = bm * 128 + lrow;
    int t = r >> 8, q = r & 255;
    const float* aptr;
    if (t == 0) aptr = query + (size_t)q * D_DIM;
    else        aptr = mem + (size_t)g_topk[q * TOPK + t - 1] * D_DIM;
    aptr += kh * 64;

    float acc[2][8][4];
#pragma unroll
    for (int a = 0; a < 2; a++)
#pragma unroll
        for (int p = 0; p < 8; p++)
#pragma unroll
            for (int rr = 0; rr < 4; rr++) acc[a][p][rr] = 0.f;

#pragma unroll 1
    for (int c = 0; c < 3; c++) {
        __syncthreads();
#pragma unroll
        for (int i = 0; i < 8; i++) {
            int idx = i * 256 + tid;
            int row = idx >> 4, s = idx & 15;
            uint32_t d = sb + (uint32_t)(row * 272 + s * 16);
            size_t go = (size_t)(bn * 128 + row) * D_DIM + c * 128 + s * 8;
            CPA16(d + XP_BHI, (const void*)(g_wcat_h + go));
            CPA16(d + XP_BLO, (const void*)(g_wcat_l + go));
        }
        CPA_COMMIT();
        {
            char* ah = smem + XP_AHI;
            char* al = smem + XP_ALO;
            const float4* src = (const float4*)(aptr + c * 128);
#pragma unroll
            for (int i = 0; i < 16; i++) {
                float4 v = src[i];
                uint32_t h0, l0, h1, l1;
                splt2(v.x, v.y, h0, l0);
                splt2(v.z, v.w, h1, l1);
                uint32_t so = (uint32_t)(lrow * 272 + kh * 128 + i * 8);
                *(uint2*)(ah + so) = make_uint2(h0, h1);
                *(uint2*)(al + so) = make_uint2(l0, l1);
            }
        }
        CPA_WAIT0();
        __syncthreads();

        const uint32_t aB = sb + XP_AHI + (uint32_t)((wm * 32 + (l & 15)) * 272 + (l >> 4) * 16);
        const uint32_t bB = sb + XP_BHI + (uint32_t)((wn * 64 + (l & 15)) * 272 + (l >> 4) * 16);
#pragma unroll 1
        for (int kk = 0; kk < 8; kk++) {
            uint32_t bh[16], bl[16];
#pragma unroll
            for (int pp = 0; pp < 4; pp++) {
                uint32_t ba = bB + (uint32_t)(pp * 16 * 272 + kk * 32);
                ldsm4(bh + pp * 4, ba);
                ldsm4(bl + pp * 4, ba + (XP_BLO - XP_BHI));
            }
#pragma unroll
            for (int a = 0; a < 2; a++) {
                uint32_t ah4[4], al4[4];
                uint32_t aa = aB + (uint32_t)(a * 16 * 272 + kk * 32);
                ldsm4(ah4, aa);
                ldsm4(al4, aa + (XP_ALO - XP_AHI));
#pragma unroll
                for (int p = 0; p < 8; p++) {
                    int pp = p >> 1, hi = p & 1;
                    mma16816(acc[a][p], ah4, bh[pp * 4 + hi], bh[pp * 4 + hi + 2]);
                    mma16816(acc[a][p], ah4, bl[pp * 4 + hi], bl[pp * 4 + hi + 2]);
                    mma16816(acc[a][p], al4, bh[pp * 4 + hi], bh[pp * 4 + hi + 2]);
                }
            }
        }
    }

    const bool fuse_h0 = (bm < 2) && (bn < 4);
#pragma unroll
    for (int a = 0; a < 2; a++) {
        int rA = bm * 128 + wm * 32 + a * 16 + (l >> 2);
#pragma unroll
        for (int p = 0; p < 8; p++) {
            int cg = bn * 128 + wn * 64 + p * 8 + (l & 3) * 2;
            float b0 = (cg < 512) ? bih[cg] : gb[cg - 512];
            float b1 = (cg < 512) ? bih[cg + 1] : gb[cg + 1 - 512];
            float v00 = acc[a][p][0] + b0, v01 = acc[a][p][1] + b1;
            float v10 = acc[a][p][2] + b0, v11 = acc[a][p][3] + b1;
            g_xp[(size_t)rA * 1024 + cg]           = v00;
            g_xp[(size_t)rA * 1024 + cg + 1]       = v01;
            g_xp[(size_t)(rA + 8) * 1024 + cg]     = v10;
            g_xp[(size_t)(rA + 8) * 1024 + cg + 1] = v11;
            if (fuse_h0) {
                float bh0 = bhh[cg], bh1 = bhh[cg + 1];
                float h00 = tanhf(v00 + bh0), h01 = tanhf(v01 + bh1);
                float h10 = tanhf(v10 + bh0), h11 = tanhf(v11 + bh1);
                size_t o0 = (size_t)rA * H_DIM + cg;
                size_t o1 = (size_t)(rA + 8) * H_DIM + cg;
                __nv_bfloat16 q00 = __float2bfloat16(h00), q01 = __float2bfloat16(h01);
                __nv_bfloat16 q10 = __float2bfloat16(h10), q11 = __float2bfloat16(h11);
                g_hbh[0][o0] = q00; g_hbh[0][o0 + 1] = q01;
                g_hbh[0][o1] = q10; g_hbh[0][o1 + 1] = q11;
                g_hbl[0][o0] = __float2bfloat16(h00 - __bfloat162float(q00));
                g_hbl[0][o0 + 1] = __float2bfloat16(h01 - __bfloat162float(q01));
                g_hbl[0][o1] = __float2bfloat16(h10 - __bfloat162float(q10));
                g_hbl[0][o1 + 1] = __float2bfloat16(h11 - __bfloat162float(q11));
            }
        }
    }
}

// ---------------- kernel D3: recurrence step GEMM, 32 CTAs, double-buffered ----------------
// t==5: gate mix fused, writes final output.
#define ST2_AHI 0
#define ST2_ALO 17408
#define ST2_BHI 34816
#define ST2_BLO 52224
#define ST2_STG 69632
#define ST2_SMEM (2 * ST2_STG)   // 139264

__global__ __launch_bounds__(256, 1) void k_step(int t, const float* __restrict__ bhh,
                                                 float* __restrict__ out) {
    extern __shared__ char smem[];
    const uint32_t sb = smem_u32(smem);
    const int tid = threadIdx.x, l = tid & 31, w = tid >> 5;
    const int wm = w & 3, wn = w >> 2;   // warp tile 16 x 32
    const int mt = blockIdx.x, nt = blockIdx.y;   // (4, 8)
    const int bin = (t + 1) & 1, bout = t & 1;
    const __nv_bfloat16* Ah = g_hbh[bin];
    const __nv_bfloat16* Al = g_hbl[bin];

    float acc[4][4];
#pragma unroll
    for (int p = 0; p < 4; p++)
#pragma unroll
        for (int rr = 0; rr < 4; rr++) acc[p][rr] = 0.f;

#define ST_LOAD(cc) do {                                                      \
    uint32_t stn = sb + ((cc) & 1) * ST2_STG;                                 \
    _Pragma("unroll")                                                         \
    for (int i = 0; i < 4; i++) {                                             \
        int idx = i * 256 + tid;                                              \
        int row = idx >> 4, s = idx & 15;                                     \
        uint32_t d = stn + (uint32_t)(row * 272 + s * 16);                    \
        size_t goA = (size_t)(mt * 64 + row) * H_DIM + (cc) * 128 + s * 8;    \
        size_t goB = (size_t)(nt * 64 + row) * H_DIM + (cc) * 128 + s * 8;    \
        CPA16(d + ST2_AHI, (const void*)(Ah + goA));                          \
        CPA16(d + ST2_ALO, (const void*)(Al + goA));                          \
        CPA16(d + ST2_BHI, (const void*)(g_whh_h + goB));                     \
        CPA16(d + ST2_BLO, (const void*)(g_whh_l + goB));                     \
    }                                                                         \
    CPA_COMMIT();                                                             \
} while (0)

    ST_LOAD(0);

#pragma unroll 1
    for (int c = 0; c < 4; c++) {
        __syncthreads();
        if (c < 3) ST_LOAD(c + 1);
        if (c < 3) CPA_WAIT1(); else CPA_WAIT0();
        __syncthreads();

        const uint32_t st = sb + (c & 1) * ST2_STG;
        const uint32_t aB = st + ST2_AHI + (uint32_t)((wm * 16 + (l & 15)) * 272 + (l >> 4) * 16);
        const uint32_t bB = st + ST2_BHI + (uint32_t)((wn * 32 + (l & 15)) * 272 + (l >> 4) * 16);
#pragma unroll 1
        for (int kk = 0; kk < 8; kk++) {
            uint32_t bh[8], bl[8];
#pragma unroll
            for (int pp = 0; pp < 2; pp++) {
                uint32_t ba = bB + (uint32_t)(pp * 16 * 272 + kk * 32);
                ldsm4(bh + pp * 4, ba);
                ldsm4(bl + pp * 4, ba + (ST2_BLO - ST2_BHI));
            }
            uint32_t ah4[4], al4[4];
            ldsm4(ah4, aB + (uint32_t)(kk * 32));
            ldsm4(al4, aB + (uint32_t)(kk * 32) + (ST2_ALO - ST2_AHI));
#pragma unroll
            for (int p = 0; p < 4; p++) {
                int pp = p >> 1, hi = p & 1;
                mma16816(acc[p], ah4, bh[pp * 4 + hi], bh[pp * 4 + hi + 2]);
                mma16816(acc[p], ah4, bl[pp * 4 + hi], bl[pp * 4 + hi + 2]);
                mma16816(acc[p], al4, bh[pp * 4 + hi], bh[pp * 4 + hi + 2]);
            }
        }
    }

    int q0 = mt * 64 + wm * 16 + (l >> 2);
#pragma unroll
    for (int p = 0; p < 4; p++) {
        int h = nt * 64 + wn * 32 + p * 8 + (l & 3) * 2;
#pragma unroll
        for (int rr = 0; rr < 4; rr++) {
            int qq = q0 + ((rr >> 1) ? 8 : 0);
            int hh = h + (rr & 1);
            float v = acc[p][rr] + g_xp[(size_t)(t * 256 + qq) * 1024 + hh] + bhh[hh];
            float ht = tanhf(v);
            if (t == TOPK) {
                float gpre = g_xp[(size_t)qq * 1024 + 512 + hh];
                float g = 1.0f / (1.0f + expf(-gpre));
                float proj = g_xp[(size_t)qq * 1024 + hh];
                out[(size_t)qq * H_DIM + hh] = g * ht + (1.0f - g) * proj;
            } else {
                size_t o = (size_t)qq * H_DIM + hh;
                __nv_bfloat16 hb = __float2bfloat16(ht);
                g_hbh[bout][o] = hb;
                g_hbl[bout][o] = __float2bfloat16(ht - __bfloat162float(hb));
            }
        }
    }
#undef ST_LOAD
}

// ---------------- launch ----------------
extern "C" void kernel_launch(void* const* d_in, const int* in_sizes, int n_in,
                              void* d_out, int out_size) {
    const float* query  = (const float*)d_in[0];
    const float* mem    = (const float*)d_in[1];
    const float* coords = (const float*)d_in[2];
    const float* sw     = (const float*)d_in[3];
    const float* Wih    = (const float*)d_in[4];
    const float* bih    = (const float*)d_in[5];
    const float* Whh    = (const float*)d_in[6];
    const float* bhh    = (const float*)d_in[7];
    const float* gW     = (const float*)d_in[8];
    const float* gb     = (const float*)d_in[9];
    float* out = (float*)d_out;

    cudaFuncSetAttribute(k_sims_mma, cudaFuncAttributeMaxDynamicSharedMemorySize, SIMS_SMEM);
    cudaFuncSetAttribute(k_xproj,    cudaFuncAttributeMaxDynamicSharedMemorySize, XP_SMEM);
    cudaFuncSetAttribute(k_step,     cudaFuncAttributeMaxDynamicSharedMemorySize, ST2_SMEM);

    // k_sims as launch #4 -> lands in the ncu capture window
    k_actc<<<(M_MEM + 255) / 256, 256>>>(coords, sw);
    k_qnorm<<<B_Q, 128>>>(query);
    k_prep<<<(H_DIM * H_DIM + 1024 * D_DIM + 255) / 256, 256>>>(Whh, Wih, gW);
    k_sims_mma<<<NSLAB2, 256, SIMS_SMEM>>>(mem);
    k_mergeref<<<B_Q, 256>>>(query, mem);
    k_xproj<<<dim3(12, 8), 256, XP_SMEM>>>(query, mem, bih, gb, bhh);
    for (int t = 1; t <= TOPK; t++)
        k_step<<<dim3(4, 8), 256, ST2_SMEM>>>(t, bhh, out);
}

// round 17
// speedup vs baseline: 1.1534x; 1.0049x over previous
#include <cuda_runtime.h>
#include <cuda_bf16.h>
#include <math.h>
#include <stdint.h>

// Problem constants
#define B_Q   256
#define M_MEM 200000
#define D_DIM 384
#define H_DIM 512
#define TOPK  5
#define KC    16
#define NC    3                         // candidates kept per slab
#define TM2   64
#define NSLAB2 3125                     // 200000 / 64 exactly

// ---------------- device scratch ----------------
__device__ float g_act[M_MEM];
__device__ __align__(16) __nv_bfloat16 g_qhi[B_Q * D_DIM];
// packed candidates: [q][slab] records of 8 floats (3 val, 3 idx-bits, 2 pad)
__device__ __align__(16) float g_candT[(size_t)B_Q * NSLAB2 * 8];
__device__ int   g_topk[B_Q * TOPK];
// RNN path scratch
__device__ __align__(16) __nv_bfloat16 g_whh_h[H_DIM * H_DIM];
__device__ __align__(16) __nv_bfloat16 g_whh_l[H_DIM * H_DIM];
__device__ __align__(16) __nv_bfloat16 g_wcat_h[1024 * D_DIM];
__device__ __align__(16) __nv_bfloat16 g_wcat_l[1024 * D_DIM];
__device__ float g_xp[1536 * 1024];
__device__ __align__(16) __nv_bfloat16 g_hbh[2][B_Q * H_DIM];
__device__ __align__(16) __nv_bfloat16 g_hbl[2][B_Q * H_DIM];

// ---------------- helpers ----------------
__device__ __forceinline__ uint32_t smem_u32(const void* p) {
    uint32_t a;
    asm("{ .reg .u64 t; cvta.to.shared.u64 t, %1; cvt.u32.u64 %0, t; }" : "=r"(a) : "l"(p));
    return a;
}
#define CPA16(s, g)  asm volatile("cp.async.cg.shared.global [%0], [%1], 16;" :: "r"(s), "l"(g) : "memory")
#define CPA_COMMIT() asm volatile("cp.async.commit_group;" ::: "memory")
#define CPA_WAIT0()  asm volatile("cp.async.wait_group 0;" ::: "memory")
#define CPA_WAIT1()  asm volatile("cp.async.wait_group 1;" ::: "memory")

__device__ __forceinline__ void ldsm4(uint32_t* r, uint32_t addr) {
    asm volatile("ldmatrix.sync.aligned.m8n8.x4.shared.b16 {%0,%1,%2,%3}, [%4];"
        : "=r"(r[0]), "=r"(r[1]), "=r"(r[2]), "=r"(r[3]) : "r"(addr));
}
__device__ __forceinline__ void mma16816(float* d, const uint32_t* a, uint32_t b0, uint32_t b1) {
    asm volatile("mma.sync.aligned.m16n8k16.row.col.f32.bf16.bf16.f32 "
        "{%0,%1,%2,%3}, {%4,%5,%6,%7}, {%8,%9}, {%0,%1,%2,%3};"
        : "+f"(d[0]), "+f"(d[1]), "+f"(d[2]), "+f"(d[3])
        : "r"(a[0]), "r"(a[1]), "r"(a[2]), "r"(a[3]), "r"(b0), "r"(b1));
}
__device__ __forceinline__ void splt2(float x, float y, uint32_t& hw, uint32_t& lw) {
    __nv_bfloat16 hx = __float2bfloat16(x), hy = __float2bfloat16(y);
    __nv_bfloat16 lx = __float2bfloat16(x - __bfloat162float(hx));
    __nv_bfloat16 ly = __float2bfloat16(y - __bfloat162float(hy));
    __nv_bfloat162 hp = __halves2bfloat162(hx, hy);
    __nv_bfloat162 lp = __halves2bfloat162(lx, ly);
    hw = *(uint32_t*)&hp; lw = *(uint32_t*)&lp;
}
__device__ __forceinline__ uint32_t pk2hi(float x, float y) {
    __nv_bfloat162 hp = __halves2bfloat162(__float2bfloat16(x), __float2bfloat16(y));
    return *(uint32_t*)&hp;
}

__device__ __forceinline__ bool better(float v, int i, float w, int j) {
    return (v > w) || (v == w && i < j);
}
template <int K>
__device__ __forceinline__ void insK(float v, int i, float* tv, int* ti) {
    if (!better(v, i, tv[K - 1], ti[K - 1])) return;
#pragma unroll
    for (int r = 0; r < K; r++) {
        if (better(v, i, tv[r], ti[r])) {
            float fv = tv[r]; int fi = ti[r];
            tv[r] = v; ti[r] = i;
            v = fv; i = fi;
        }
    }
}
#define ins5 insK<TOPK>

// ---------------- kernel A1: center (redundant per block) + activations ----------------
__global__ void k_actc(const float* __restrict__ coords, const float* __restrict__ sw) {
    __shared__ float sx[256], sy[256];
    int tid = threadIdx.x;
    float x = 0.f, y = 0.f;
    for (int i = tid; i < H_DIM; i += 256) { x += sw[2 * i]; y += sw[2 * i + 1]; }
    sx[tid] = x; sy[tid] = y;
    __syncthreads();
    for (int o = 128; o > 0; o >>= 1) {
        if (tid < o) { sx[tid] += sx[tid + o]; sy[tid] += sy[tid + o]; }
        __syncthreads();
    }
    float cx = sx[0] / (float)H_DIM, cy = sy[0] / (float)H_DIM;
    int i = blockIdx.x * blockDim.x + tid;
    if (i < M_MEM) {
        float dx = coords[2 * i] - cx;
        float dy = coords[2 * i + 1] - cy;
        g_act[i] = 1.0f / (1.0f + sqrtf(dx * dx + dy * dy));
    }
}

// ---------------- kernel A2: normalize queries -> bf16 hi ----------------
__global__ void k_qnorm(const float* __restrict__ q) {
    __shared__ float red[128];
    int b = blockIdx.x, tid = threadIdx.x;
    float s = 0.f;
    for (int d = tid; d < D_DIM; d += 128) {
        float v = q[(size_t)b * D_DIM + d];
        s += v * v;
    }
    red[tid] = s;
    __syncthreads();
    for (int o = 64; o > 0; o >>= 1) {
        if (tid < o) red[tid] += red[tid + o];
        __syncthreads();
    }
    float r = 1.0f / fmaxf(sqrtf(red[0]), 1e-8f);
    for (int d = tid; d < D_DIM; d += 128)
        g_qhi[(size_t)b * D_DIM + d] = __float2bfloat16(q[(size_t)b * D_DIM + d] * r);
}

// ---------------- kernel A3: weight split prep ----------------
__global__ void k_prep(const float* __restrict__ Whh, const float* __restrict__ Wih,
                       const float* __restrict__ gW) {
    int i = blockIdx.x * blockDim.x + threadIdx.x;
    if (i < H_DIM * H_DIM) {
        float v = Whh[i];
        __nv_bfloat16 h = __float2bfloat16(v);
        g_whh_h[i] = h;
        g_whh_l[i] = __float2bfloat16(v - __bfloat162float(h));
    } else if (i < H_DIM * H_DIM + 1024 * D_DIM) {
        int j = i - H_DIM * H_DIM;
        int row = j / D_DIM, col = j % D_DIM;
        float v = (row < 512) ? Wih[row * D_DIM + col] : gW[(row - 512) * D_DIM + col];
        __nv_bfloat16 h = __float2bfloat16(v);
        g_wcat_h[j] = h;
        g_wcat_l[j] = __float2bfloat16(v - __bfloat162float(h));
    }
}

// ---------------- kernel B: 1-term coarse sims, TM=64, 2 CTAs/SM (R14 mainloop) ----------------
// single stage: A 64x272 at 1024, B 256x272 at 18432. total smem 88064.
#define SA3   1024
#define SB3   18432
#define SIMS_SMEM 88064
#define E_STG 1024                      // epilogue staging: 256 x 68 f32 = 69632

__global__ __launch_bounds__(256, 2) void k_sims_mma(const float* __restrict__ mem) {
    extern __shared__ char smem[];
    const uint32_t sb = smem_u32(smem);
    float* s_rn  = (float*)smem;                 // 64 f32
    float* s_act = (float*)(smem + 256);         // 64 f32

    const int tid = threadIdx.x;
    const int l   = tid & 31;
    const int w   = tid >> 5;       // 0..7
    const int wm  = w & 1;          // rows wm*32..+32
    const int wn  = w >> 1;         // queries wn*64..+64
    const int m0  = blockIdx.x * TM2;

    if (tid < 64) s_act[tid] = g_act[m0 + tid];

    float acc[2][8][4];
#pragma unroll
    for (int a = 0; a < 2; a++)
#pragma unroll
        for (int p = 0; p < 8; p++)
#pragma unroll
            for (int r = 0; r < 4; r++) acc[a][p][r] = 0.f;

    // A coalesced: warp w owns rows w*8..w*8+7
    const int ar0 = w * 8;
    const float* abase = mem + (size_t)(m0 + ar0) * D_DIM + l * 4;
    float nsq8[8];
#pragma unroll
    for (int r = 0; r < 8; r++) nsq8[r] = 0.f;

    const uint32_t aB0 = sb + SA3 + (uint32_t)((wm * 32 + (l & 15)) * 272 + (l >> 4) * 16);
    const uint32_t bB0 = sb + SB3 + (uint32_t)((wn * 64 + (l & 15)) * 272 + (l >> 4) * 16);
    const int phase = blockIdx.x & 1;

#pragma unroll 1
    for (int ci = 0; ci < 3; ci++) {
        const int c = (ci + phase) % 3;   // desynchronize partner CTAs

        // B chunk via cp.async (L2-hot)
#pragma unroll
        for (int i = 0; i < 16; i++) {
            int idx = i * 256 + tid;
            int row = idx >> 4, s = idx & 15;
            size_t go = (size_t)row * D_DIM + c * 128 + s * 8;
            CPA16(sb + SB3 + (uint32_t)(row * 272 + s * 16), (const void*)(g_qhi + go));
        }
        CPA_COMMIT();

        // A chunk: coalesced LDG.128 per row, convert, STS
        {
            float4 av[8];
#pragma unroll
            for (int r = 0; r < 8; r++)
                av[r] = *(const float4*)(abase + (size_t)r * D_DIM + c * 128);
#pragma unroll
            for (int r = 0; r < 8; r++) {
                float4 v = av[r];
                nsq8[r] += v.x * v.x + v.y * v.y + v.z * v.z + v.w * v.w;
                uint32_t h0 = pk2hi(v.x, v.y), h1 = pk2hi(v.z, v.w);
                *(uint2*)(smem + SA3 + (ar0 + r) * 272 + l * 8) = make_uint2(h0, h1);
            }
        }
        CPA_WAIT0();
        __syncthreads();

        // GEMM: 8 k16 steps
#pragma unroll
        for (int kk = 0; kk < 8; kk++) {
            uint32_t bh[16];
#pragma unroll
            for (int pp = 0; pp < 4; pp++)
                ldsm4(bh + pp * 4, bB0 + (uint32_t)(pp * 16 * 272 + kk * 32));
#pragma unroll
            for (int a = 0; a < 2; a++) {
                uint32_t ah4[4];
                ldsm4(ah4, aB0 + (uint32_t)(a * 16 * 272 + kk * 32));
#pragma unroll
                for (int p = 0; p < 8; p++) {
                    int pp = p >> 1, hi = p & 1;
                    mma16816(acc[a][p], ah4, bh[pp * 4 + hi], bh[pp * 4 + hi + 2]);
                }
            }
        }
        __syncthreads();   // all reads done before next chunk overwrites stage
    }

    // ---- norms: per-row warp reduction ----
#pragma unroll
    for (int r = 0; r < 8; r++) {
        float s = nsq8[r];
#pragma unroll
        for (int o = 16; o > 0; o >>= 1) s += __shfl_xor_sync(0xffffffff, s, o);
        if (l == 0) s_rn[ar0 + r] = 1.0f / fmaxf(sqrtf(s), 1e-8f);
    }
    __syncthreads();

    // ---- epilogue: scale + bias, stage query-major [256][68] ----
    float* stg = (float*)(smem + E_STG);
#pragma unroll
    for (int a = 0; a < 2; a++) {
        int mA = wm * 32 + a * 16 + (l >> 2);
        float rnA = s_rn[mA],     acA = s_act[mA];
        float rnB = s_rn[mA + 8], acB = s_act[mA + 8];
#pragma unroll
        for (int p = 0; p < 8; p++) {
            int q = wn * 64 + p * 8 + (l & 3) * 2;
            stg[q * 68 + mA]           = acc[a][p][0] * rnA + acA;
            stg[(q + 1) * 68 + mA]     = acc[a][p][1] * rnA + acA;
            stg[q * 68 + mA + 8]       = acc[a][p][2] * rnB + acB;
            stg[(q + 1) * 68 + mA + 8] = acc[a][p][3] * rnB + acB;
        }
    }
    __syncthreads();

    // ---- top-3 with per-float4 threshold batch; packed 32B transposed store ----
    {
        const int q = tid;
        float tv[NC]; int ti[NC];
#pragma unroll
        for (int r = 0; r < NC; r++) { tv[r] = -3.4e38f; ti[r] = 0x7fffffff; }
        const float4* col = (const float4*)(stg + q * 68);
#pragma unroll 4
        for (int i = 0; i < 16; i++) {
            float4 v = col[i];
            float mx = fmaxf(fmaxf(v.x, v.y), fmaxf(v.z, v.w));
            if (mx >= tv[NC - 1]) {     // conservative: ties may still insert by index
                int mb = m0 + i * 4;
                insK<NC>(v.x, mb,     tv, ti);
                insK<NC>(v.y, mb + 1, tv, ti);
                insK<NC>(v.z, mb + 2, tv, ti);
                insK<NC>(v.w, mb + 3, tv, ti);
            }
        }
        float4* rec = (float4*)(g_candT + ((size_t)q * NSLAB2 + blockIdx.x) * 8);
        rec[0] = make_float4(tv[0], tv[1], tv[2], __int_as_float(ti[0]));
        rec[1] = make_float4(__int_as_float(ti[1]), __int_as_float(ti[2]), 0.f, 0.f);
    }
}

// ---------------- kernel C: fused merge -> top-16 -> exact refine -> top-5 ----------------
template <int K>
__device__ __forceinline__ void mergeK(float* av, int* ai, const float* bv, const int* bi) {
    float ov[K]; int oi[K];
    int ia = 0, ib = 0;
#pragma unroll
    for (int r = 0; r < K; r++) {
        bool ta = (ib >= K) || (ia < K && better(av[ia], ai[ia], bv[ib], bi[ib]));
        if (ta) { ov[r] = av[ia]; oi[r] = ai[ia]; ia++; }
        else    { ov[r] = bv[ib]; oi[r] = bi[ib]; ib++; }
    }
#pragma unroll
    for (int r = 0; r < K; r++) { av[r] = ov[r]; ai[r] = oi[r]; }
}

__global__ __launch_bounds__(256) void k_mergeref(const float* __restrict__ query,
                                                 const float* __restrict__ mem) {
    __shared__ float sv[256][KC];
    __shared__ int   si[256][KC];
    __shared__ float qv[D_DIM];
    __shared__ float s_qn[8];
    __shared__ float s_sims[KC];

    const int q = blockIdx.x, tid = threadIdx.x;
    const int lane = tid & 31, wr = tid >> 5;

    float p = 0.f;
    for (int d = tid; d < D_DIM; d += 256) {
        float v = query[(size_t)q * D_DIM + d];
        qv[d] = v;
        p += v * v;
    }
#pragma unroll
    for (int o = 16; o > 0; o >>= 1) p += __shfl_xor_sync(0xffffffff, p, o);
    if (lane == 0) s_qn[wr] = p;

    // phase 1: coalesced scan of packed 32B candidate records
    float tv[KC]; int ti[KC];
#pragma unroll
    for (int r = 0; r < KC; r++) { tv[r] = -3.4e38f; ti[r] = 0x7fffffff; }
    const float* qbase = g_candT + (size_t)q * NSLAB2 * 8;
    for (int s = tid; s < NSLAB2; s += 256) {
        const float4* rec = (const float4*)(qbase + (size_t)s * 8);
        float4 r0 = rec[0], r1 = rec[1];
        insK<KC>(r0.x, __float_as_int(r0.w), tv, ti);
        insK<KC>(r0.y, __float_as_int(r1.x), tv, ti);
        insK<KC>(r0.z, __float_as_int(r1.y), tv, ti);
    }
#pragma unroll
    for (int r = 0; r < KC; r++) { sv[tid][r] = tv[r]; si[tid][r] = ti[r]; }
    __syncthreads();
    for (int o = 128; o > 0; o >>= 1) {
        if (tid < o) mergeK<KC>(sv[tid], si[tid], sv[tid + o], si[tid + o]);
        __syncthreads();
    }

    float qs = 0.f;
#pragma unroll
    for (int i = 0; i < 8; i++) qs += s_qn[i];
    float rq = 1.0f / fmaxf(sqrtf(qs), 1e-8f);

    for (int c = wr; c < KC; c += 8) {
        int mi = si[0][c];
        const float* mv = mem + (size_t)mi * D_DIM;
        float dot = 0.f, msq = 0.f;
        for (int d = lane; d < D_DIM; d += 32) {
            float m = mv[d];
            dot += qv[d] * m;
            msq += m * m;
        }
#pragma unroll
        for (int o = 16; o > 0; o >>= 1) {
            dot += __shfl_xor_sync(0xffffffff, dot, o);
            msq += __shfl_xor_sync(0xffffffff, msq, o);
        }
        if (lane == 0)
            s_sims[c] = dot * rq / fmaxf(sqrtf(msq), 1e-8f) + g_act[mi];
    }
    __syncthreads();

    if (tid == 0) {
        float fv[TOPK]; int fi[TOPK];
#pragma unroll
        for (int r = 0; r < TOPK; r++) { fv[r] = -3.4e38f; fi[r] = 0x7fffffff; }
        for (int c = 0; c < KC; c++)
            ins5(s_sims[c], si[0][c], fv, fi);
#pragma unroll
        for (int r = 0; r < TOPK; r++)
            g_topk[q * TOPK + r] = fi[r];
    }
}

// ---------------- kernel D1: x_proj + gate GEMM [1536 x 1024 x 384], fused h0 ----------------
#define XP_AHI 0
#define XP_ALO 34816
#define XP_BHI 69632
#define XP_BLO 104448
#define XP_SMEM 139264

__global__ __launch_bounds__(256, 1) void k_xproj(
    const float* __restrict__ query, const float* __restrict__ mem,
    const float* __restrict__ bih, const float* __restrict__ gb,
    const float* __restrict__ bhh)
{
    extern __shared__ char smem[];
    const uint32_t sb = smem_u32(smem);
    const int tid = threadIdx.x, l = tid & 31, w = tid >> 5;
    const int wm = w & 3, wn = w >> 2;
    const int bm = blockIdx.x, bn = blockIdx.y;

    const int lrow = tid >> 1, kh = tid & 1;
    int r = bm * 128 + lrow;
    int t = r >> 8, q = r & 255;
    const float* aptr;
    if (t == 0) aptr = query + (size_t)q * D_DIM;
    else        aptr = mem + (size_t)g_topk[q * TOPK + t - 1] * D_DIM;
    aptr += kh * 64;

    float acc[2][8][4];
#pragma unroll
    for (int a = 0; a < 2; a++)
#pragma unroll
        for (int p = 0; p < 8; p++)
#pragma unroll
            for (int rr = 0; rr < 4; rr++) acc[a][p][rr] = 0.f;

#pragma unroll 1
    for (int c = 0; c < 3; c++) {
        __syncthreads();
#pragma unroll
        for (int i = 0; i < 8; i++) {
            int idx = i * 256 + tid;
            int row = idx >> 4, s = idx & 15;
            uint32_t d = sb + (uint32_t)(row * 272 + s * 16);
            size_t go = (size_t)(bn * 128 + row) * D_DIM + c * 128 + s * 8;
            CPA16(d + XP_BHI, (const void*)(g_wcat_h + go));
            CPA16(d + XP_BLO, (const void*)(g_wcat_l + go));
        }
        CPA_COMMIT();
        {
            char* ah = smem + XP_AHI;
            char* al = smem + XP_ALO;
            const float4* src = (const float4*)(aptr + c * 128);
#pragma unroll
            for (int i = 0; i < 16; i++) {
                float4 v = src[i];
                uint32_t h0, l0, h1, l1;
                splt2(v.x, v.y, h0, l0);
                splt2(v.z, v.w, h1, l1);
                uint32_t so = (uint32_t)(lrow * 272 + kh * 128 + i * 8);
                *(uint2*)(ah + so) = make_uint2(h0, h1);
                *(uint2*)(al + so) = make_uint2(l0, l1);
            }
        }
        CPA_WAIT0();
        __syncthreads();

        const uint32_t aB = sb + XP_AHI + (uint32_t)((wm * 32 + (l & 15)) * 272 + (l >> 4) * 16);
        const uint32_t bB = sb + XP_BHI + (uint32_t)((wn * 64 + (l & 15)) * 272 + (l >> 4) * 16);
#pragma unroll 1
        for (int kk = 0; kk < 8; kk++) {
            uint32_t bh[16], bl[16];
#pragma unroll
            for (int pp = 0; pp < 4; pp++) {
                uint32_t ba = bB + (uint32_t)(pp * 16 * 272 + kk * 32);
                ldsm4(bh + pp * 4, ba);
                ldsm4(bl + pp * 4, ba + (XP_BLO - XP_BHI));
            }
#pragma unroll
            for (int a = 0; a < 2; a++) {
                uint32_t ah4[4], al4[4];
                uint32_t aa = aB + (uint32_t)(a * 16 * 272 + kk * 32);
                ldsm4(ah4, aa);
                ldsm4(al4, aa + (XP_ALO - XP_AHI));
#pragma unroll
                for (int p = 0; p < 8; p++) {
                    int pp = p >> 1, hi = p & 1;
                    mma16816(acc[a][p], ah4, bh[pp * 4 + hi], bh[pp * 4 + hi + 2]);
                    mma16816(acc[a][p], ah4, bl[pp * 4 + hi], bl[pp * 4 + hi + 2]);
                    mma16816(acc[a][p], al4, bh[pp * 4 + hi], bh[pp * 4 + hi + 2]);
                }
            }
        }
    }

    const bool fuse_h0 = (bm < 2) && (bn < 4);
#pragma unroll
    for (int a = 0; a < 2; a++) {
        int rA = bm * 128 + wm * 32 + a * 16 + (l >> 2);
#pragma unroll
        for (int p = 0; p < 8; p++) {
            int cg = bn * 128 + wn * 64 + p * 8 + (l & 3) * 2;
            float b0 = (cg < 512) ? bih[cg] : gb[cg - 512];
            float b1 = (cg < 512) ? bih[cg + 1] : gb[cg + 1 - 512];
            float v00 = acc[a][p][0] + b0, v01 = acc[a][p][1] + b1;
            float v10 = acc[a][p][2] + b0, v11 = acc[a][p][3] + b1;
            g_xp[(size_t)rA * 1024 + cg]           = v00;
            g_xp[(size_t)rA * 1024 + cg + 1]       = v01;
            g_xp[(size_t)(rA + 8) * 1024 + cg]     = v10;
            g_xp[(size_t)(rA + 8) * 1024 + cg + 1] = v11;
            if (fuse_h0) {
                float bh0 = bhh[cg], bh1 = bhh[cg + 1];
                float h00 = tanhf(v00 + bh0), h01 = tanhf(v01 + bh1);
                float h10 = tanhf(v10 + bh0), h11 = tanhf(v11 + bh1);
                size_t o0 = (size_t)rA * H_DIM + cg;
                size_t o1 = (size_t)(rA + 8) * H_DIM + cg;
                __nv_bfloat16 q00 = __float2bfloat16(h00), q01 = __float2bfloat16(h01);
                __nv_bfloat16 q10 = __float2bfloat16(h10), q11 = __float2bfloat16(h11);
                g_hbh[0][o0] = q00; g_hbh[0][o0 + 1] = q01;
                g_hbh[0][o1] = q10; g_hbh[0][o1 + 1] = q11;
                g_hbl[0][o0] = __float2bfloat16(h00 - __bfloat162float(q00));
                g_hbl[0][o0 + 1] = __float2bfloat16(h01 - __bfloat162float(q01));
                g_hbl[0][o1] = __float2bfloat16(h10 - __bfloat162float(q10));
                g_hbl[0][o1 + 1] = __float2bfloat16(h11 - __bfloat162float(q11));
            }
        }
    }
}

// ---------------- kernel D3: recurrence step GEMM, 32 CTAs, double-buffered ----------------
// t==5: gate mix fused, writes final output.
#define ST2_AHI 0
#define ST2_ALO 17408
#define ST2_BHI 34816
#define ST2_BLO 52224
#define ST2_STG 69632
#define ST2_SMEM (2 * ST2_STG)   // 139264

__global__ __launch_bounds__(256, 1) void k_step(int t, const float* __restrict__ bhh,
                                                 float* __restrict__ out) {
    extern __shared__ char smem[];
    const uint32_t sb = smem_u32(smem);
    const int tid = threadIdx.x, l = tid & 31, w = tid >> 5;
    const int wm = w & 3, wn = w >> 2;   // warp tile 16 x 32
    const int mt = blockIdx.x, nt = blockIdx.y;   // (4, 8)
    const int bin = (t + 1) & 1, bout = t & 1;
    const __nv_bfloat16* Ah = g_hbh[bin];
    const __nv_bfloat16* Al = g_hbl[bin];

    float acc[4][4];
#pragma unroll
    for (int p = 0; p < 4; p++)
#pragma unroll
        for (int rr = 0; rr < 4; rr++) acc[p][rr] = 0.f;

#define ST_LOAD(cc) do {                                                      \
    uint32_t stn = sb + ((cc) & 1) * ST2_STG;                                 \
    _Pragma("unroll")                                                         \
    for (int i = 0; i < 4; i++) {                                             \
        int idx = i * 256 + tid;                                              \
        int row = idx >> 4, s = idx & 15;                                     \
        uint32_t d = stn + (uint32_t)(row * 272 + s * 16);                    \
        size_t goA = (size_t)(mt * 64 + row) * H_DIM + (cc) * 128 + s * 8;    \
        size_t goB = (size_t)(nt * 64 + row) * H_DIM + (cc) * 128 + s * 8;    \
        CPA16(d + ST2_AHI, (const void*)(Ah + goA));                          \
        CPA16(d + ST2_ALO, (const void*)(Al + goA));                          \
        CPA16(d + ST2_BHI, (const void*)(g_whh_h + goB));                     \
        CPA16(d + ST2_BLO, (const void*)(g_whh_l + goB));                     \
    }                                                                         \
    CPA_COMMIT();                                                             \
} while (0)

    ST_LOAD(0);

#pragma unroll 1
    for (int c = 0; c < 4; c++) {
        __syncthreads();
        if (c < 3) ST_LOAD(c + 1);
        if (c < 3) CPA_WAIT1(); else CPA_WAIT0();
        __syncthreads();

        const uint32_t st = sb + (c & 1) * ST2_STG;
        const uint32_t aB = st + ST2_AHI + (uint32_t)((wm * 16 + (l & 15)) * 272 + (l >> 4) * 16);
        const uint32_t bB = st + ST2_BHI + (uint32_t)((wn * 32 + (l & 15)) * 272 + (l >> 4) * 16);
#pragma unroll 1
        for (int kk = 0; kk < 8; kk++) {
            uint32_t bh[8], bl[8];
#pragma unroll
            for (int pp = 0; pp < 2; pp++) {
                uint32_t ba = bB + (uint32_t)(pp * 16 * 272 + kk * 32);
                ldsm4(bh + pp * 4, ba);
                ldsm4(bl + pp * 4, ba + (ST2_BLO - ST2_BHI));
            }
            uint32_t ah4[4], al4[4];
            ldsm4(ah4, aB + (uint32_t)(kk * 32));
            ldsm4(al4, aB + (uint32_t)(kk * 32) + (ST2_ALO - ST2_AHI));
#pragma unroll
            for (int p = 0; p < 4; p++) {
                int pp = p >> 1, hi = p & 1;
                mma16816(acc[p], ah4, bh[pp * 4 + hi], bh[pp * 4 + hi + 2]);
                mma16816(acc[p], ah4, bl[pp * 4 + hi], bl[pp * 4 + hi + 2]);
                mma16816(acc[p], al4, bh[pp * 4 + hi], bh[pp * 4 + hi + 2]);
            }
        }
    }

    int q0 = mt * 64 + wm * 16 + (l >> 2);
#pragma unroll
    for (int p = 0; p < 4; p++) {
        int h = nt * 64 + wn * 32 + p * 8 + (l & 3) * 2;
#pragma unroll
        for (int rr = 0; rr < 4; rr++) {
            int qq = q0 + ((rr >> 1) ? 8 : 0);
            int hh = h + (rr & 1);
            float v = acc[p][rr] + g_xp[(size_t)(t * 256 + qq) * 1024 + hh] + bhh[hh];
            float ht = tanhf(v);
            if (t == TOPK) {
                float gpre = g_xp[(size_t)qq * 1024 + 512 + hh];
                float g = 1.0f / (1.0f + expf(-gpre));
                float proj = g_xp[(size_t)qq * 1024 + hh];
                out[(size_t)qq * H_DIM + hh] = g * ht + (1.0f - g) * proj;
            } else {
                size_t o = (size_t)qq * H_DIM + hh;
                __nv_bfloat16 hb = __float2bfloat16(ht);
                g_hbh[bout][o] = hb;
                g_hbl[bout][o] = __float2bfloat16(ht - __bfloat162float(hb));
            }
        }
    }
#undef ST_LOAD
}

// ---------------- launch ----------------
extern "C" void kernel_launch(void* const* d_in, const int* in_sizes, int n_in,
                              void* d_out, int out_size) {
    const float* query  = (const float*)d_in[0];
    const float* mem    = (const float*)d_in[1];
    const float* coords = (const float*)d_in[2];
    const float* sw     = (const float*)d_in[3];
    const float* Wih    = (const float*)d_in[4];
    const float* bih    = (const float*)d_in[5];
    const float* Whh    = (const float*)d_in[6];
    const float* bhh    = (const float*)d_in[7];
    const float* gW     = (const float*)d_in[8];
    const float* gb     = (const float*)d_in[9];
    float* out = (float*)d_out;

    cudaFuncSetAttribute(k_sims_mma, cudaFuncAttributeMaxDynamicSharedMemorySize, SIMS_SMEM);
    cudaFuncSetAttribute(k_xproj,    cudaFuncAttributeMaxDynamicSharedMemorySize, XP_SMEM);
    cudaFuncSetAttribute(k_step,     cudaFuncAttributeMaxDynamicSharedMemorySize, ST2_SMEM);

    // k_mergeref as launch #4 -> lands in the ncu capture window this round
    k_actc<<<(M_MEM + 255) / 256, 256>>>(coords, sw);
    k_qnorm<<<B_Q, 128>>>(query);
    k_sims_mma<<<NSLAB2, 256, SIMS_SMEM>>>(mem);
    k_mergeref<<<B_Q, 256>>>(query, mem);
    k_prep<<<(H_DIM * H_DIM + 1024 * D_DIM + 255) / 256, 256>>>(Whh, Wih, gW);
    k_xproj<<<dim3(12, 8), 256, XP_SMEM>>>(query, mem, bih, gb, bhh);
    for (int t = 1; t <= TOPK; t++)
        k_step<<<dim3(4, 8), 256, ST2_SMEM>>>(t, bhh, out);
}